// round 17
// baseline (speedup 1.0000x reference)
#include <cuda_runtime.h>
#include <cuda_bf16.h>
#include <stdint.h>
#include <math.h>

// Problem constants
#define BB 4
#define SS 2048
#define DD 1024
#define HH 16
#define DK 64
#define MM (BB * SS)          // 8192 rows
#define NEG_BIG (-1.0e30f)
// softmax scale with log2(e) folded in: 0.125 * 1.44269504
#define QSCALE 0.1803368801111137f
#define KVSZ 131072           // floats per (b,h) packed K or V (2048*64)

// ---------------- scratch (alloc-free: __device__ globals) ----------------
__device__ float g_q[BB * HH * SS * DK];     // [b,h,s,dk]  (pre-scaled, tf32)
__device__ float g_k[BB * HH * SS * DK];     // packed-B per (b,h): n=s, k=d
__device__ float g_v[BB * HH * SS * DK];     // packed-B per (b,h): n=d, k=s
__device__ float g_attn[MM * DD];            // packed-A layout (tf32)
__device__ float g_xt[MM * DD];              // packed-A layout (tf32)
__device__ float g_w4[4 * DD * DD];          // packed-B layout (tf32)

// ---------------- helpers ----------------
__device__ __forceinline__ unsigned f2tf32(float f) {
    unsigned r;
    asm("cvt.rna.tf32.f32 %0, %1;" : "=r"(r) : "f"(f));
    return r;
}
__device__ __forceinline__ float f2tf32f(float f) {
    return __uint_as_float(f2tf32(f));
}
__device__ __forceinline__ float ex2(float x) {
    float y;
    asm("ex2.approx.f32 %0, %1;" : "=f"(y) : "f"(x));
    return y;
}

__device__ __forceinline__ void mma_m16n8k8(float* d, const unsigned* a,
                                            const unsigned* b) {
    asm volatile(
        "mma.sync.aligned.m16n8k8.row.col.f32.tf32.tf32.f32 "
        "{%0,%1,%2,%3},{%4,%5,%6,%7},{%8,%9},{%0,%1,%2,%3};\n"
        : "+f"(d[0]), "+f"(d[1]), "+f"(d[2]), "+f"(d[3])
        : "r"(a[0]), "r"(a[1]), "r"(a[2]), "r"(a[3]), "r"(b[0]), "r"(b[1]));
}

__device__ __forceinline__ void cp16(void* smem, const void* gmem) {
    unsigned s = (unsigned)__cvta_generic_to_shared(smem);
    asm volatile("cp.async.cg.shared.global [%0], [%1], 16;\n" :: "r"(s), "l"(gmem));
}

// packed-A address: element (r, c); k-tiles per row = 128 (K=1024)
__device__ __forceinline__ size_t packA_addr(int r, int c) {
    return ((size_t)((r >> 4) * 128 + (c >> 3)) << 7) +
           ((r & 7) * 16 + (c & 3) * 4 + ((r >> 3) & 1) + 2 * ((c >> 2) & 1));
}
// packed-B element address within one (b,h) K buffer: n=s (2048), k=d (64)
__device__ __forceinline__ size_t packK_addr(int s, int d) {
    return ((size_t)((s >> 4) * 8 + (d >> 3)) << 7) +
           ((s & 7) * 16 + (d & 3) * 4 + ((d >> 2) & 1) + 2 * ((s >> 3) & 1));
}
// packed-B element address within one (b,h) V buffer: n=d (64), k=s (2048)
__device__ __forceinline__ size_t packV_addr(int d, int s) {
    return ((size_t)((s >> 3) * 4 + (d >> 4)) << 7) +
           ((d & 7) * 16 + (s & 3) * 4 + ((s >> 2) & 1) + 2 * ((d >> 3) & 1));
}

// ---------------- pre-pass: pack X (A layout) ----------------
__global__ void pack_a_kernel(const float* __restrict__ A, float* __restrict__ out,
                              int n4) {
    int i = blockIdx.x * blockDim.x + threadIdx.x;
    if (i >= n4) return;
    int tm = i >> 12;
    int tk = (i >> 5) & 127;
    int lane = i & 31;
    int g = lane >> 2, tig = lane & 3;
    int r0 = tm * 16, c0 = tk * 8;
    const float* p = A + (size_t)r0 * DD + c0;
    float4 v;
    v.x = f2tf32f(p[(size_t)g * DD + tig]);
    v.y = f2tf32f(p[(size_t)(g + 8) * DD + tig]);
    v.z = f2tf32f(p[(size_t)g * DD + tig + 4]);
    v.w = f2tf32f(p[(size_t)(g + 8) * DD + tig + 4]);
    ((float4*)out)[i] = v;
}

// ---------------- pre-pass: pack 4 weights (B layout) ----------------
__global__ void pack_w4_kernel(const float* __restrict__ w0,
                               const float* __restrict__ w1,
                               const float* __restrict__ w2,
                               const float* __restrict__ w3,
                               float* __restrict__ out) {
    const int per_w = DD * DD / 4;
    int j = blockIdx.x * blockDim.x + threadIdx.x;
    if (j >= 4 * per_w) return;
    int w = j / per_w, i = j - w * per_w;
    const float* W = (w == 0) ? w0 : (w == 1) ? w1 : (w == 2) ? w2 : w3;
    int tn = i >> 12;
    int tk = (i >> 5) & 127;
    int lane = i & 31;
    int g = lane >> 2, tig = lane & 3;
    int n0 = tn * 16, k0 = tk * 8;
    const float* p = W + (size_t)n0 * DD + k0;
    float4 v;
    v.x = f2tf32f(p[(size_t)g * DD + tig]);
    v.y = f2tf32f(p[(size_t)g * DD + tig + 4]);
    v.z = f2tf32f(p[(size_t)(g + 8) * DD + tig]);
    v.w = f2tf32f(p[(size_t)(g + 8) * DD + tig + 4]);
    ((float4*)(out + (size_t)w * DD * DD))[j - w * per_w] = v;
}

// ---------------- GEMM core: packed A x packed B -> C ----------------
// BM=BN=128, BK=32, 3-stage cp.async, explicit fragment double-buffering.
// MODE 0: C row-major [M,1024]. MODE 1: QKV epilogue scatter.
#define GSTG 3
#define STGF 4096          // floats per stage per operand (128x32)

template <int MODE>
__global__ __launch_bounds__(256, 2) void gemm_pk(const float* __restrict__ A,
                                                  const float* __restrict__ W,
                                                  float* __restrict__ C0,
                                                  float* __restrict__ C1,
                                                  float* __restrict__ C2) {
    extern __shared__ float gsm[];
    float* As = gsm;                      // [GSTG][8 m-tiles][4 k-tiles][128]
    float* Bs = gsm + GSTG * STGF;

    const int tid = threadIdx.x;
    const int lane = tid & 31;
    const int wid = tid >> 5;
    const int g = lane >> 2;
    const int tig = lane & 3;
    const int wm0 = (wid >> 2) * 64;
    const int wn0 = (wid & 3) * 32;
    const int row0 = blockIdx.y * 128;
    const int col0 = blockIdx.x * 128;

    const float* Abase = A + (size_t)(row0 >> 4) * 16384;
    const float* Wbase = W + (size_t)(col0 >> 4) * 16384;

    float acc[4][4][4];
#pragma unroll
    for (int im = 0; im < 4; im++)
#pragma unroll
        for (int jn = 0; jn < 4; jn++)
#pragma unroll
            for (int q = 0; q < 4; q++) acc[im][jn][q] = 0.0f;

    const int NK = DD / 32;   // 32 iterations of BK=32

    // prologue: stages 0,1
#pragma unroll
    for (int s = 0; s < 2; s++) {
#pragma unroll
        for (int h = 0; h < 4; h++) {
            int c = tid + h * 256;
            int tm_l = c >> 7;
            int r = c & 127;
            int kk = r >> 5, f4 = r & 31;
            size_t go = (size_t)tm_l * 16384 + (size_t)(s * 4 + kk) * 128 + f4 * 4;
            cp16(As + s * STGF + c * 4, Abase + go);
            cp16(Bs + s * STGF + c * 4, Wbase + go);
        }
        asm volatile("cp.async.commit_group;\n");
    }

    for (int kt = 0; kt < NK; kt++) {
        if (kt < NK - 1) asm volatile("cp.async.wait_group 1;\n");
        else             asm volatile("cp.async.wait_group 0;\n");
        __syncthreads();

        if (kt + 2 < NK) {
            const int nxt = (kt + 2) % 3;
#pragma unroll
            for (int h = 0; h < 4; h++) {
                int c = tid + h * 256;
                int tm_l = c >> 7;
                int r = c & 127;
                int kk = r >> 5, f4 = r & 31;
                size_t go = (size_t)tm_l * 16384 +
                            (size_t)((kt + 2) * 4 + kk) * 128 + f4 * 4;
                cp16(As + nxt * STGF + c * 4, Abase + go);
                cp16(Bs + nxt * STGF + c * 4, Wbase + go);
            }
            asm volatile("cp.async.commit_group;\n");
        }

        const float* Ac = As + (kt % 3) * STGF;
        const float* Bc = Bs + (kt % 3) * STGF;

        // explicit fragment double-buffering across the 4 kk-steps
        float4 ca[4], cb[2], na[4], nb[2];
#pragma unroll
        for (int im = 0; im < 4; im++)
            ca[im] = *(const float4*)(Ac + (((wm0 >> 4) + im) * 4 + 0) * 128 +
                                      lane * 4);
#pragma unroll
        for (int p = 0; p < 2; p++)
            cb[p] = *(const float4*)(Bc + (((wn0 >> 4) + p) * 4 + 0) * 128 +
                                     lane * 4);

#pragma unroll
        for (int kk = 0; kk < 4; kk++) {
            if (kk < 3) {
#pragma unroll
                for (int im = 0; im < 4; im++)
                    na[im] = *(const float4*)(Ac + (((wm0 >> 4) + im) * 4 + kk + 1) * 128 +
                                              lane * 4);
#pragma unroll
                for (int p = 0; p < 2; p++)
                    nb[p] = *(const float4*)(Bc + (((wn0 >> 4) + p) * 4 + kk + 1) * 128 +
                                             lane * 4);
            }
#pragma unroll
            for (int im = 0; im < 4; im++) {
                const unsigned* a = (const unsigned*)&ca[im];
#pragma unroll
                for (int jn = 0; jn < 4; jn++) {
                    const unsigned* bp = (const unsigned*)&cb[jn >> 1];
                    unsigned b[2] = {bp[(jn & 1) * 2], bp[(jn & 1) * 2 + 1]};
                    mma_m16n8k8(acc[im][jn], a, b);
                }
            }
            if (kk < 3) {
#pragma unroll
                for (int im = 0; im < 4; im++) ca[im] = na[im];
#pragma unroll
                for (int p = 0; p < 2; p++) cb[p] = nb[p];
            }
        }
    }

#pragma unroll
    for (int im = 0; im < 4; im++) {
#pragma unroll
        for (int jn = 0; jn < 4; jn++) {
            int r = row0 + wm0 + im * 16 + g;
            int c = col0 + wn0 + jn * 8 + 2 * tig;
#pragma unroll
            for (int half = 0; half < 2; half++) {
                int rr = r + half * 8;
                float2 v = make_float2(acc[im][jn][half * 2 + 0],
                                       acc[im][jn][half * 2 + 1]);
                if (MODE == 1) {
                    int w = c >> 10;
                    int cl = c & 1023;
                    int b = rr >> 11;
                    int s = rr & 2047;
                    int h = cl >> 6;
                    int d = cl & 63;
                    if (w == 0) {
                        v.x = f2tf32f(v.x * QSCALE);
                        v.y = f2tf32f(v.y * QSCALE);
                        size_t off = (((size_t)(b * HH + h) * SS + s) * DK + d);
                        *(float2*)(C0 + off) = v;
                    } else if (w == 1) {
                        float* dst = C1 + (size_t)(b * HH + h) * KVSZ;
                        dst[packK_addr(s, d)]     = f2tf32f(v.x);
                        dst[packK_addr(s, d + 1)] = f2tf32f(v.y);
                    } else {
                        float* dst = C2 + (size_t)(b * HH + h) * KVSZ;
                        dst[packV_addr(d, s)]     = f2tf32f(v.x);
                        dst[packV_addr(d + 1, s)] = f2tf32f(v.y);
                    }
                } else {
                    *(float2*)(C0 + (size_t)rr * DD + c) = v;
                }
            }
        }
    }
}

// ---------------- Flash attention (causal), packed K/V fragments ----------
// BM=128, BN=64. 8 warps; warp w owns rows [16w,16w+16).
// smem: Ps[128*68] + 2 stages x (K 4096 + V 4096) = 100352 B.
#define ALD 68

__global__ __launch_bounds__(256, 2) void attn_mma(const float* __restrict__ Q,
                                                   const float* __restrict__ K,
                                                   const float* __restrict__ V,
                                                   float* __restrict__ O) {
    extern __shared__ float sm[];
    float* Ps = sm;                     // [128][ALD]
    float* KVs = sm + 128 * ALD;        // 2 x [K:4096 | V:4096]

    const int tid = threadIdx.x;
    const int lane = tid & 31;
    const int wid = tid >> 5;
    const int g = lane >> 2;
    const int tig = lane & 3;
    const int qb = (gridDim.x - 1) - blockIdx.x;
    const int bh = blockIdx.y;
    const int q0 = qb * 128;
    const int row_base = wid * 16;

    const float* Qb = Q + (size_t)bh * SS * DK;
    const float* Kb = K + (size_t)bh * KVSZ;
    const float* Vb = V + (size_t)bh * KVSZ;

    unsigned qf[8][4];
    {
        const float* qr0 = Qb + (size_t)(q0 + row_base + g) * DK;
        const float* qr1 = Qb + (size_t)(q0 + row_base + g + 8) * DK;
#pragma unroll
        for (int s = 0; s < 8; s++) {
            int k8 = s * 8;
            qf[s][0] = __float_as_uint(qr0[k8 + tig]);
            qf[s][1] = __float_as_uint(qr1[k8 + tig]);
            qf[s][2] = __float_as_uint(qr0[k8 + tig + 4]);
            qf[s][3] = __float_as_uint(qr1[k8 + tig + 4]);
        }
    }

    float m_i[2] = {NEG_BIG, NEG_BIG};
    float l_i[2] = {0.0f, 0.0f};
    float oacc[8][4];
#pragma unroll
    for (int jn = 0; jn < 8; jn++)
#pragma unroll
        for (int q = 0; q < 4; q++) oacc[jn][q] = 0.0f;

    const int nt = 2 * qb + 2;

    auto fill = [&](int st, int kv0) {
        float* Kd = KVs + st * 8192;
        const float* ks = Kb + (size_t)(kv0 >> 4) * 1024;
        const float* vs = Vb + (size_t)(kv0 >> 3) * 512;
#pragma unroll
        for (int i = 0; i < 4; i++) {
            int idx = tid + 256 * i;
            cp16(Kd + idx * 4, ks + idx * 4);
        }
#pragma unroll
        for (int i = 0; i < 4; i++) {
            int idx = tid + 256 * i;
            cp16(Kd + 4096 + idx * 4, vs + idx * 4);
        }
        asm volatile("cp.async.commit_group;\n");
    };

    fill(0, 0);

    for (int t = 0; t < nt; t++) {
        asm volatile("cp.async.wait_group 0;\n");
        __syncthreads();

        const int cur = t & 1;
        if (t + 1 < nt) fill(cur ^ 1, (t + 1) * 64);

        const bool skip = (t == nt - 1) && (wid < 4);
        if (!skip) {
            const float* Ks = KVs + cur * 8192;
            const float* Vs = Ks + 4096;

            float sacc[8][4];
#pragma unroll
            for (int jn = 0; jn < 8; jn++)
#pragma unroll
                for (int q = 0; q < 4; q++) sacc[jn][q] = 0.0f;

#pragma unroll
            for (int s = 0; s < 8; s++) {
#pragma unroll
                for (int j16 = 0; j16 < 4; j16++) {
                    float4 b4 = *(const float4*)(Ks + (j16 * 8 + s) * 128 + lane * 4);
                    const unsigned* bp = (const unsigned*)&b4;
                    mma_m16n8k8(sacc[j16 * 2], qf[s], bp);
                    mma_m16n8k8(sacc[j16 * 2 + 1], qf[s], bp + 2);
                }
            }

            if (t >= nt - 2 && !(t == nt - 2 && wid >= 4)) {
                const int kv0 = t * 64;
#pragma unroll
                for (int jn = 0; jn < 8; jn++)
#pragma unroll
                    for (int q = 0; q < 4; q++) {
                        int row = q0 + row_base + g + (q >> 1) * 8;
                        int col = kv0 + jn * 8 + 2 * tig + (q & 1);
                        if (col > row) sacc[jn][q] = NEG_BIG;
                    }
            }

#pragma unroll
            for (int h = 0; h < 2; h++) {
                float mx = NEG_BIG;
#pragma unroll
                for (int jn = 0; jn < 8; jn++)
                    mx = fmaxf(mx, fmaxf(sacc[jn][2 * h], sacc[jn][2 * h + 1]));
                mx = fmaxf(mx, __shfl_xor_sync(0xffffffffu, mx, 1));
                mx = fmaxf(mx, __shfl_xor_sync(0xffffffffu, mx, 2));
                float mn = fmaxf(m_i[h], mx);
                float corr = ex2(m_i[h] - mn);
                m_i[h] = mn;
                float rs = 0.0f;
#pragma unroll
                for (int jn = 0; jn < 8; jn++) {
                    float e0 = ex2(sacc[jn][2 * h] - mn);
                    float e1 = ex2(sacc[jn][2 * h + 1] - mn);
                    sacc[jn][2 * h] = e0;
                    sacc[jn][2 * h + 1] = e1;
                    rs += e0 + e1;
                }
                rs += __shfl_xor_sync(0xffffffffu, rs, 1);
                rs += __shfl_xor_sync(0xffffffffu, rs, 2);
                l_i[h] = l_i[h] * corr + rs;
#pragma unroll
                for (int jn = 0; jn < 8; jn++) {
                    oacc[jn][2 * h] *= corr;
                    oacc[jn][2 * h + 1] *= corr;
                }
            }

#pragma unroll
            for (int jn = 0; jn < 8; jn++) {
                float2 p0 = make_float2(f2tf32f(sacc[jn][0]), f2tf32f(sacc[jn][1]));
                float2 p1 = make_float2(f2tf32f(sacc[jn][2]), f2tf32f(sacc[jn][3]));
                *(float2*)(Ps + (row_base + g) * ALD + jn * 8 + 2 * tig) = p0;
                *(float2*)(Ps + (row_base + g + 8) * ALD + jn * 8 + 2 * tig) = p1;
            }
            __syncwarp();

#pragma unroll
            for (int s = 0; s < 8; s++) {
                int k8 = s * 8;
                unsigned af[4];
                af[0] = __float_as_uint(Ps[(row_base + g) * ALD + k8 + tig]);
                af[1] = __float_as_uint(Ps[(row_base + g + 8) * ALD + k8 + tig]);
                af[2] = __float_as_uint(Ps[(row_base + g) * ALD + k8 + tig + 4]);
                af[3] = __float_as_uint(Ps[(row_base + g + 8) * ALD + k8 + tig + 4]);
#pragma unroll
                for (int j16 = 0; j16 < 4; j16++) {
                    float4 b4 = *(const float4*)(Vs + (s * 4 + j16) * 128 + lane * 4);
                    const unsigned* bp = (const unsigned*)&b4;
                    mma_m16n8k8(oacc[j16 * 2], af, bp);
                    mma_m16n8k8(oacc[j16 * 2 + 1], af, bp + 2);
                }
            }
            __syncwarp();
        }
    }

    // epilogue: packed-A write of O (row = b*SS+s, col = h*64+d)
    const int b = bh >> 4, h = bh & 15;
#pragma unroll
    for (int hf = 0; hf < 2; hf++) {
        float inv = 1.0f / l_i[hf];
        int s = q0 + row_base + g + hf * 8;
        int r = b * SS + s;
#pragma unroll
        for (int jn = 0; jn < 8; jn++) {
            int c = h * DK + jn * 8 + 2 * tig;
            O[packA_addr(r, c)]     = f2tf32f(oacc[jn][2 * hf] * inv);
            O[packA_addr(r, c + 1)] = f2tf32f(oacc[jn][2 * hf + 1] * inv);
        }
    }
}

// ---------------- launch ----------------
extern "C" void kernel_launch(void* const* d_in, const int* in_sizes, int n_in,
                              void* d_out, int out_size) {
    const float* x  = (const float*)d_in[0];
    const float* wq = (const float*)d_in[1];
    const float* wk = (const float*)d_in[2];
    const float* wv = (const float*)d_in[3];
    const float* wo = (const float*)d_in[4];
    float* out = (float*)d_out;

    float *pq, *pk, *pv, *pa, *pxt, *pw4;
    cudaGetSymbolAddress((void**)&pq, g_q);
    cudaGetSymbolAddress((void**)&pk, g_k);
    cudaGetSymbolAddress((void**)&pv, g_v);
    cudaGetSymbolAddress((void**)&pa, g_attn);
    cudaGetSymbolAddress((void**)&pxt, g_xt);
    cudaGetSymbolAddress((void**)&pw4, g_w4);

    static const int attn_smem = 128 * ALD * sizeof(float) + 2 * 8192 * 4; // 100352
    static const int gemm_smem = 2 * GSTG * STGF * sizeof(float);          // 98304
    cudaFuncSetAttribute(attn_mma, cudaFuncAttributeMaxDynamicSharedMemorySize,
                         attn_smem);
    cudaFuncSetAttribute(gemm_pk<0>, cudaFuncAttributeMaxDynamicSharedMemorySize,
                         gemm_smem);
    cudaFuncSetAttribute(gemm_pk<1>, cudaFuncAttributeMaxDynamicSharedMemorySize,
                         gemm_smem);

    const int n4x = MM * DD / 4;
    const int n4w4 = 4 * DD * DD / 4;
    pack_a_kernel<<<(n4x + 255) / 256, 256>>>(x, pxt, n4x);
    pack_w4_kernel<<<(n4w4 + 255) / 256, 256>>>(wq, wk, wv, wo, pw4);

    dim3 gQKV(3 * DD / 128, MM / 128);   // (24, 64)
    gemm_pk<1><<<gQKV, 256, gemm_smem>>>(pxt, pw4, pq, pk, pv);

    dim3 gAttn(SS / 128, BB * HH);       // (16, 64)
    attn_mma<<<gAttn, 256, attn_smem>>>(pq, pk, pv, pa);

    dim3 gOut(DD / 128, MM / 128);       // (8, 64)
    gemm_pk<0><<<gOut, 256, gemm_smem>>>(pa, pw4 + 3 * DD * DD, out, nullptr, nullptr);
}